// round 13
// baseline (speedup 1.0000x reference)
#include <cuda_runtime.h>
#include <cuda_fp16.h>

#define BB 8
#define TT 512
#define DD 64
#define TILE 32
#define NT (TT / TILE)               // 16 tiles per dim
#define NPAIR (NT * (NT + 1) / 2)    // 136 upper-tri tile pairs

// sqrt(log2(e)): pre-scale x so exp(-(dx)^2) = ex2(-(s*dx)^2)
#define SQRT_LOG2E 1.2011224087864498f
#define SGN2 0x80008000u

typedef unsigned long long u64;
typedef __half2 h2;

// Precomputed half-precision operands (written by v_kernel):
__device__ __half g_xh[BB * TT * DD];   // s * x   (256 KB)
__device__ __half g_vh[BB * TT * DD];   // v = xW^T + b (256 KB)

// ---- f32x2 packed helpers (v_kernel GEMM) ---------------------------------
__device__ __forceinline__ u64 pack2(float lo, float hi) {
    u64 r; asm("mov.b64 %0, {%1, %2};" : "=l"(r) : "f"(lo), "f"(hi)); return r;
}
__device__ __forceinline__ void unpack2(u64 v, float& lo, float& hi) {
    asm("mov.b64 {%0, %1}, %2;" : "=f"(lo), "=f"(hi) : "l"(v));
}
__device__ __forceinline__ u64 fma2(u64 a, u64 b, u64 c) {
    u64 r; asm("fma.rn.f32x2 %0, %1, %2, %3;" : "=l"(r) : "l"(a), "l"(b), "l"(c)); return r;
}

// ---- f16x2 helpers ---------------------------------------------------------
__device__ __forceinline__ h2 u2h(unsigned u) { return *(h2*)&u; }
// e = exp2(-(dif^2)): HMUL2 with folded source negation + ONE MUFU.EX2.
__device__ __forceinline__ h2 ex2negsq(h2 dif) {
    h2 m = __hmul2(__hneg2(dif), dif);
    unsigned r, u = *(unsigned*)&m;
    asm("ex2.approx.f16x2 %0, %1;" : "=r"(r) : "r"(u));
    return *(h2*)&r;
}

// ---------------------------------------------------------------------------
// Kernel 1: v = x @ W^T + b, plus half operand prep: g_xh = half(s*x),
// g_vh = half(v). 128 blocks x 256 threads.
// ---------------------------------------------------------------------------
#define WSTR 68
__global__ __launch_bounds__(256)
void v_kernel(const float* __restrict__ x, const float* __restrict__ W,
              const float* __restrict__ bias) {
    __shared__ float sWT[DD * WSTR];     // sWT[d*68 + e] = W[e*64 + d]
    __shared__ float sX[32 * DD];

    int tid = threadIdx.x;
    int row0 = blockIdx.x * 32;

    for (int k = tid; k < DD * DD; k += 256) {
        int e = k >> 6, d = k & 63;
        sWT[d * WSTR + e] = W[k];
    }
    for (int k = tid; k < 32 * DD; k += 256)
        sX[k] = x[row0 * DD + k];
    __syncthreads();

    // Emit g_xh = half(s*x) for these 32 rows (1024 u32 / block)
#pragma unroll
    for (int k = 0; k < 4; k++) {
        int lin = tid + 256 * k;             // [0, 1024)
        int r = lin >> 5, q = lin & 31;
        float a0 = sX[r * DD + 2 * q];
        float a1 = sX[r * DD + 2 * q + 1];
        h2 hv = __floats2half2_rn(SQRT_LOG2E * a0, SQRT_LOG2E * a1);
        ((unsigned*)g_xh)[(row0 + r) * 32 + q] = *(unsigned*)&hv;
    }

    int eg = tid & 15;                   // e = 4*eg .. 4*eg+3
    int rs = tid >> 4;                   // rows rs, rs+16
    float4 b4 = *(const float4*)&bias[4 * eg];
    u64 acc0a = pack2(b4.x, b4.y), acc0b = pack2(b4.z, b4.w);
    u64 acc1a = acc0a, acc1b = acc0b;

#pragma unroll 8
    for (int d = 0; d < DD; d++) {
        const float* wp = &sWT[d * WSTR + 4 * eg];
        u64 wA = *(const u64*)&wp[0];
        u64 wB = *(const u64*)&wp[2];
        float x0 = sX[rs * DD + d];
        float x1 = sX[(rs + 16) * DD + d];
        u64 x0p = pack2(x0, x0), x1p = pack2(x1, x1);
        acc0a = fma2(x0p, wA, acc0a);
        acc0b = fma2(x0p, wB, acc0b);
        acc1a = fma2(x1p, wA, acc1a);
        acc1b = fma2(x1p, wB, acc1b);
    }
    float o0, o1, o2, o3;
    uint2 st;
    unpack2(acc0a, o0, o1); unpack2(acc0b, o2, o3);
    { h2 pA = __floats2half2_rn(o0, o1), pB = __floats2half2_rn(o2, o3);
      st.x = *(unsigned*)&pA; st.y = *(unsigned*)&pB; }
    *(uint2*)&g_vh[(row0 + rs) * DD + 4 * eg] = st;
    unpack2(acc1a, o0, o1); unpack2(acc1b, o2, o3);
    { h2 pA = __floats2half2_rn(o0, o1), pB = __floats2half2_rn(o2, o3);
      st.x = *(unsigned*)&pA; st.y = *(unsigned*)&pB; }
    *(uint2*)&g_vh[(row0 + rs + 16) * DD + 4 * eg] = st;
}

// ---------------------------------------------------------------------------
// Kernel 2: pairwise RBF. d-PACKED f16x2 hot loop (R12 datapath) with a
// 5-CTAs/SM occupancy cap (51 regs) -> 40 resident warps/SM, fuller waves.
// Thread (tx,ty): rows {2ty,2ty+1} x cols {tx, tx+16}; [row][d] layout,
// j-arrays XOR-swizzled in 8B units -> conflict-free LDS.64.
// ---------------------------------------------------------------------------
#define OFF_VI  2048     // half offsets within shared
#define OFF_NXJ 4096
#define OFF_VJ  6144

__global__ __launch_bounds__(256, 5)
void rbf_kernel(float* __restrict__ out) {
    __shared__ __align__(16) __half Sh[8192];   // 16 KB: XI | VI | NXJ | VJ

    int b = blockIdx.y;
    int p = blockIdx.x;
    int ti = 0, rem = p;
    while (rem >= NT - ti) { rem -= NT - ti; ti++; }
    int tj = ti + rem;
    int i0 = ti * TILE, j0 = tj * TILE;

    int tid = threadIdx.x;
    const unsigned* gx = (const unsigned*)g_xh;
    const unsigned* gv = (const unsigned*)g_vh;
    unsigned* S32 = (unsigned*)Sh;
    int baseI = (b * TT + i0) * 32;
    int baseJ = (b * TT + j0) * 32;

    // Stage: each thread owns u32s [4*tid, 4*tid+4) = row r, quads q0..q0+3.
    {
        int r = tid >> 3, q0 = (tid & 7) * 4;
        int lin = r * 32 + q0;
        uint4 xi4 = *(const uint4*)&gx[baseI + lin];
        uint4 vi4 = *(const uint4*)&gv[baseI + lin];
        uint4 xj4 = *(const uint4*)&gx[baseJ + lin];
        uint4 vj4 = *(const uint4*)&gv[baseJ + lin];

        *(uint4*)&S32[lin] = xi4;                         // XI linear
        *(uint4*)&S32[(OFF_VI >> 1) + lin] = vi4;         // VI linear

        int msk = r & 15;
        int u0 = (q0 >> 1) ^ msk;        // swizzled 8B slot for (q0,q0+1)
        int u1 = u0 ^ 1;                 // slot for (q0+2,q0+3)
        *(uint2*)&S32[(OFF_NXJ >> 1) + r * 32 + 2 * u0] =
            make_uint2(xj4.x ^ SGN2, xj4.y ^ SGN2);       // -s*xj
        *(uint2*)&S32[(OFF_NXJ >> 1) + r * 32 + 2 * u1] =
            make_uint2(xj4.z ^ SGN2, xj4.w ^ SGN2);
        *(uint2*)&S32[(OFF_VJ >> 1) + r * 32 + 2 * u0] = make_uint2(vj4.x, vj4.y);
        *(uint2*)&S32[(OFF_VJ >> 1) + r * 32 + 2 * u1] = make_uint2(vj4.z, vj4.w);
    }
    __syncthreads();

    int tx = tid & 15, ty = tid >> 4;
    const __half* pi = Sh + 2 * ty * 64;             // XI row 2ty (VI at +OFF_VI)
    const __half* pj = Sh + OFF_NXJ + tx * 64;       // NXJ col tx (VJ at +2048)

    float denF[2][2], niF[2][2], njF[2][2];
#pragma unroll
    for (int r = 0; r < 2; r++)
#pragma unroll
        for (int c = 0; c < 2; c++) { denF[r][c] = 0.f; niF[r][c] = 0.f; njF[r][c] = 0.f; }

#pragma unroll
    for (int ch = 0; ch < 2; ch++) {         // 2 chunks of 32 d
        h2 dH[2][2], nH[2][2], qH[2][2];
        h2 z = __float2half2_rn(0.f);
#pragma unroll
        for (int r = 0; r < 2; r++)
#pragma unroll
            for (int c = 0; c < 2; c++) { dH[r][c] = z; nH[r][c] = z; qH[r][c] = z; }

#pragma unroll
        for (int s = 0; s < 8; s++) {        // 4 d's per step
            int u = ch * 8 + s;
            int uj = u ^ tx;                  // swizzled 8B slot for j-arrays

            uint2 fiA = *(const uint2*)(pi + 4 * u);                 // row 2ty
            uint2 fiB = *(const uint2*)(pi + 64 + 4 * u);            // row 2ty+1
            uint2 fvA = *(const uint2*)(pi + OFF_VI + 4 * u);
            uint2 fvB = *(const uint2*)(pi + OFF_VI + 64 + 4 * u);
            uint2 njA = *(const uint2*)(pj + 4 * uj);                // col tx
            uint2 njB = *(const uint2*)(pj + 1024 + 4 * uj);         // col tx+16
            uint2 jvA = *(const uint2*)(pj + 2048 + 4 * uj);
            uint2 jvB = *(const uint2*)(pj + 2048 + 1024 + 4 * uj);

            h2 fi[2][2] = {{u2h(fiA.x), u2h(fiA.y)}, {u2h(fiB.x), u2h(fiB.y)}};
            h2 fv[2][2] = {{u2h(fvA.x), u2h(fvA.y)}, {u2h(fvB.x), u2h(fvB.y)}};
            h2 nj[2][2] = {{u2h(njA.x), u2h(njA.y)}, {u2h(njB.x), u2h(njB.y)}};
            h2 jv[2][2] = {{u2h(jvA.x), u2h(jvA.y)}, {u2h(jvB.x), u2h(jvB.y)}};

#pragma unroll
            for (int r = 0; r < 2; r++)
#pragma unroll
                for (int c = 0; c < 2; c++)
#pragma unroll
                    for (int s2 = 0; s2 < 2; s2++) {
                        h2 dif = __hadd2(fi[r][s2], nj[c][s2]);   // s*(xi-xj)
                        h2 e   = ex2negsq(dif);                   // HMUL2(neg)+MUFU
                        dH[r][c] = __hadd2(dH[r][c], e);
                        nH[r][c] = __hfma2(e, fv[r][s2], nH[r][c]);
                        qH[r][c] = __hfma2(e, jv[c][s2], qH[r][c]);
                    }
        }

        // fold chunk partials (lo+hi are different d's of the same pair)
#pragma unroll
        for (int r = 0; r < 2; r++)
#pragma unroll
            for (int c = 0; c < 2; c++) {
                float2 t;
                t = __half22float2(dH[r][c]); denF[r][c] += t.x + t.y;
                t = __half22float2(nH[r][c]); niF[r][c]  += t.x + t.y;
                t = __half22float2(qH[r][c]); njF[r][c]  += t.x + t.y;
            }
    }

    float* ob = out + (size_t)b * TT * TT;

#pragma unroll
    for (int r = 0; r < 2; r++) {
        int gi = i0 + 2 * ty + r;
#pragma unroll
        for (int c = 0; c < 2; c++) {
            int gj = j0 + tx + 16 * c;
            float rc;
            asm("rcp.approx.ftz.f32 %0, %1;" : "=f"(rc) : "f"(denF[r][c]));
            ob[(size_t)gi * TT + gj] = niF[r][c] * rc;   // coalesced across tx
            if (ti != tj)
                ob[(size_t)gj * TT + gi] = njF[r][c] * rc;   // mirror
        }
    }
}

extern "C" void kernel_launch(void* const* d_in, const int* in_sizes, int n_in,
                              void* d_out, int out_size) {
    const float* x = (const float*)d_in[0];    // (8,512,64)
    const float* W = (const float*)d_in[1];    // (64,64)
    const float* bias = (const float*)d_in[2]; // (64,)
    float* out = (float*)d_out;                // (8,512,512)

    v_kernel<<<(BB * TT) / 32, 256>>>(x, W, bias);
    rbf_kernel<<<dim3(NPAIR, BB), 256>>>(out);
}